// round 8
// baseline (speedup 1.0000x reference)
#include <cuda_runtime.h>
#include <cstdint>

#define BATCH 8
#define SEQ   512
#define DM    512

// ---------------------------------------------------------------------------
// Scratch, stored with within-8-group k-permutation so mma fragment pairs
// (k, k+4) are adjacent: perm(k) = (k & ~7) | ((k&3)<<1) | ((k>>2)&1)
// ---------------------------------------------------------------------------
__device__ __align__(128) float g_Qr[BATCH * SEQ * DM];
__device__ __align__(128) float g_Kr[BATCH * SEQ * DM];
__device__ __align__(128) float g_C [BATCH * SEQ * DM];
__device__ __align__(128) float g_Et[SEQ * DM];

__device__ __forceinline__ int perm8(int k) {
    return (k & ~7) | ((k & 3) << 1) | ((k >> 2) & 1);
}

// cvt.rna.tf32.f32 destination is .b32 (PTX ISA)
__device__ __forceinline__ float rna_tf32(float x) {
    uint32_t r;
    asm("cvt.rna.tf32.f32 %0, %1;" : "=r"(r) : "f"(x));
    return __uint_as_float(r);
}

__device__ __forceinline__ void cpa16(uint32_t dst, const void* src) {
    asm volatile("cp.async.cg.shared.global [%0], [%1], 16;" :: "r"(dst), "l"(src));
}
__device__ __forceinline__ void cpa_commit() {
    asm volatile("cp.async.commit_group;" ::: "memory");
}
template <int N> __device__ __forceinline__ void cpa_wait() {
    asm volatile("cp.async.wait_group %0;" :: "n"(N) : "memory");
}
__device__ __forceinline__ uint32_t smem_u32(const void* p) {
    uint32_t a;
    asm("{ .reg .u64 t; cvta.to.shared.u64 t, %1; cvt.u32.u64 %0, t; }" : "=r"(a) : "l"(p));
    return a;
}

__device__ __forceinline__ void mma_m16n8k8(float* d, const uint32_t* a, const uint32_t* b) {
    asm volatile(
        "mma.sync.aligned.m16n8k8.row.col.f32.tf32.tf32.f32 "
        "{%0,%1,%2,%3}, {%4,%5,%6,%7}, {%8,%9}, {%0,%1,%2,%3};"
        : "+f"(d[0]), "+f"(d[1]), "+f"(d[2]), "+f"(d[3])
        : "r"(a[0]), "r"(a[1]), "r"(a[2]), "r"(a[3]), "r"(b[0]), "r"(b[1]));
}

// ---------------------------------------------------------------------------
// Merged prep kernel (unchanged from R7 — it works)
// ---------------------------------------------------------------------------
__global__ __launch_bounds__(128) void prep_kernel(const float* __restrict__ q,
                                                   const float* __restrict__ k,
                                                   const float* __restrict__ E) {
    const int row = blockIdx.x;
    const int i   = row & (SEQ - 1);
    const float* __restrict__ qrow = q    + (size_t)row * DM;
    const float* __restrict__ krow = k    + (size_t)row * DM;
    float* __restrict__ qr         = g_Qr + (size_t)row * DM;
    float* __restrict__ kr         = g_Kr + (size_t)row * DM;
    float* __restrict__ cr         = g_C  + (size_t)row * DM;

    __shared__ float sq[DM];
    __shared__ float red[128];
    const int t = threadIdx.x;

    float partial = 0.0f;
    #pragma unroll
    for (int j = t; j < DM; j += 128) {
        float v = qrow[j];
        sq[j] = v;
        qr[perm8(j)] = rna_tf32(v);
        kr[perm8(j)] = rna_tf32(krow[j]);
        if (j >= i) partial += v;
    }
    red[t] = partial;
    __syncthreads();
    #pragma unroll
    for (int s = 64; s > 0; s >>= 1) {
        if (t < s) red[t] += red[t + s];
        __syncthreads();
    }
    const float suffix = red[0];

    #pragma unroll
    for (int m = t; m < DM; m += 128) {
        float v = (m == 0) ? suffix : ((m <= i) ? sq[i - m] : 0.0f);
        cr[perm8(m)] = rna_tf32(v);
    }

    if (row < SEQ) {   // transpose E: Et[n=row][perm(m)] = rna(E[m][n])
        float* __restrict__ et = g_Et + (size_t)row * DM;
        #pragma unroll
        for (int m = t; m < DM; m += 128)
            et[perm8(m)] = rna_tf32(E[(size_t)m * DM + row]);
    }
}

// ---------------------------------------------------------------------------
// Main GEMM: 128x64 CTA tile, BK=32, 3-stage cp.async, 8 warps (2 M x 4 N),
// warp tile 64x16. Two CTAs per SM (occ 25%) so one CTA's MMA burst covers
// the other's barrier/load phase.
// ---------------------------------------------------------------------------
#define BM 128
#define BN 64
#define BKF 32
#define ROWSZ 40                        // 32 data floats + 8 pad (conflict-free LDS.64)
#define ATILEF (BM * ROWSZ)             // 5120 floats
#define BTILEF (BN * ROWSZ)             // 2560 floats
#define STAGEF (ATILEF + BTILEF)        // 7680 floats
#define NSTAGE 3
#define SMEM_BYTES (NSTAGE * STAGEF * 4)   // 92,160 B

__device__ __forceinline__ void load_stage(int s, int buf, int b, int m0, int n0,
                                           uint32_t smem_base, int tid) {
    const int kg0 = (s & 15) * BKF;
    const float* Asrc;
    const float* Bsrc;
    if (s < 16) {
        Asrc = g_Qr + ((size_t)(b * SEQ + m0)) * DM + kg0;
        Bsrc = g_Kr + ((size_t)(b * SEQ + n0)) * DM + kg0;
    } else {
        Asrc = g_C  + ((size_t)(b * SEQ + m0)) * DM + kg0;
        Bsrc = g_Et + (size_t)n0 * DM + kg0;
    }
    const uint32_t abase = smem_base + buf * (STAGEF * 4);
    const uint32_t bbase = abase + ATILEF * 4;

    // A tile: 128 rows x 8 float4 chunks = 1024; 256 threads x 4
    #pragma unroll
    for (int i = 0; i < 4; i++) {
        const int e = tid + i * 256;
        const int r = e >> 3;
        const int f = e & 7;
        cpa16(abase + (uint32_t)(r * ROWSZ + f * 4) * 4, Asrc + (size_t)r * DM + f * 4);
    }
    // B tile: 64 rows x 8 chunks = 512; 256 threads x 2
    #pragma unroll
    for (int i = 0; i < 2; i++) {
        const int e = tid + i * 256;
        const int r = e >> 3;
        const int f = e & 7;
        cpa16(bbase + (uint32_t)(r * ROWSZ + f * 4) * 4, Bsrc + (size_t)r * DM + f * 4);
    }
}

struct Frag {
    uint32_t a[4][4];
    uint32_t b[2][2];
};

__device__ __forceinline__ void load_frag(Frag& fr, const float* As, const float* Bs,
                                          int k8, int wm, int wn, int grp, int qk) {
    const int kp = k8 * 8 + qk * 2;     // permuted position of (kk, kk+4)
    #pragma unroll
    for (int mi = 0; mi < 4; mi++) {
        const int mrow = wm + mi * 16 + grp;
        const float2 lo = *reinterpret_cast<const float2*>(&As[mrow * ROWSZ + kp]);
        const float2 hi = *reinterpret_cast<const float2*>(&As[(mrow + 8) * ROWSZ + kp]);
        fr.a[mi][0] = __float_as_uint(lo.x);
        fr.a[mi][1] = __float_as_uint(hi.x);
        fr.a[mi][2] = __float_as_uint(lo.y);
        fr.a[mi][3] = __float_as_uint(hi.y);
    }
    #pragma unroll
    for (int ni = 0; ni < 2; ni++) {
        const int ncol = wn + ni * 8 + grp;
        const float2 bb = *reinterpret_cast<const float2*>(&Bs[ncol * ROWSZ + kp]);
        fr.b[ni][0] = __float_as_uint(bb.x);
        fr.b[ni][1] = __float_as_uint(bb.y);
    }
}

__global__ __launch_bounds__(256, 2) void gemm_kernel(float* __restrict__ out) {
    extern __shared__ __align__(16) float smem[];
    const uint32_t smem_base = smem_u32(smem);
    const int tid  = threadIdx.x;
    const int wid  = tid >> 5;
    const int lane = tid & 31;
    const int b  = blockIdx.z;
    const int m0 = blockIdx.y * BM;
    const int n0 = blockIdx.x * BN;

    const int wm = (wid >> 2) * 64;     // 0 or 64
    const int wn = (wid & 3) * 16;      // 0,16,32,48
    const int grp = lane >> 2;
    const int qk  = lane & 3;

    float acc[4][2][4];
    #pragma unroll
    for (int mi = 0; mi < 4; mi++)
        #pragma unroll
        for (int ni = 0; ni < 2; ni++)
            #pragma unroll
            for (int r = 0; r < 4; r++) acc[mi][ni][r] = 0.0f;

    load_stage(0, 0, b, m0, n0, smem_base, tid); cpa_commit();
    load_stage(1, 1, b, m0, n0, smem_base, tid); cpa_commit();

    Frag fr[2];

    #pragma unroll 1
    for (int s = 0; s < 32; s++) {
        if (s >= 30) cpa_wait<0>(); else cpa_wait<1>();
        __syncthreads();
        if (s + 2 < 32) {
            load_stage(s + 2, (s + 2) % 3, b, m0, n0, smem_base, tid);
            cpa_commit();
        }

        const int buf = s - (s / 3) * 3;
        const float* As = smem + buf * STAGEF;
        const float* Bs = As + ATILEF;

        load_frag(fr[0], As, Bs, 0, wm, wn, grp, qk);
        #pragma unroll
        for (int k8 = 0; k8 < 4; k8++) {
            if (k8 < 3)
                load_frag(fr[(k8 + 1) & 1], As, Bs, k8 + 1, wm, wn, grp, qk);
            const Frag& f = fr[k8 & 1];
            #pragma unroll
            for (int mi = 0; mi < 4; mi++)
                #pragma unroll
                for (int ni = 0; ni < 2; ni++)
                    mma_m16n8k8(acc[mi][ni], f.a[mi], f.b[ni]);
        }
    }

    // epilogue
    float* __restrict__ Ob = out + (size_t)b * SEQ * SEQ;
    #pragma unroll
    for (int mi = 0; mi < 4; mi++) {
        const int mr = m0 + wm + mi * 16 + grp;
        #pragma unroll
        for (int ni = 0; ni < 2; ni++) {
            const int nc = n0 + wn + ni * 8 + qk * 2;
            float2 v0 = make_float2(acc[mi][ni][0], acc[mi][ni][1]);
            float2 v1 = make_float2(acc[mi][ni][2], acc[mi][ni][3]);
            *reinterpret_cast<float2*>(&Ob[(size_t)mr * SEQ + nc]) = v0;
            *reinterpret_cast<float2*>(&Ob[(size_t)(mr + 8) * SEQ + nc]) = v1;
        }
    }
}

// ---------------------------------------------------------------------------
extern "C" void kernel_launch(void* const* d_in, const int* in_sizes, int n_in,
                              void* d_out, int out_size) {
    const float* q = (const float*)d_in[0];
    const float* k = (const float*)d_in[1];
    const float* E = (const float*)d_in[2];
    float* out = (float*)d_out;

    cudaFuncSetAttribute(gemm_kernel, cudaFuncAttributeMaxDynamicSharedMemorySize, SMEM_BYTES);

    prep_kernel<<<BATCH * SEQ, 128>>>(q, k, E);

    dim3 grid(SEQ / BN, SEQ / BM, BATCH);
    gemm_kernel<<<grid, 256, SMEM_BYTES>>>(out);
}

// round 9
// speedup vs baseline: 1.0188x; 1.0188x over previous
#include <cuda_runtime.h>
#include <cstdint>

#define BATCH 8
#define SEQ   512
#define DM    512

// ---------------------------------------------------------------------------
// Scratch, stored with within-8-group k-permutation so mma fragment pairs
// (k, k+4) are adjacent: perm(k) = (k & ~7) | ((k&3)<<1) | ((k>>2)&1)
// ---------------------------------------------------------------------------
__device__ __align__(128) float g_Qr[BATCH * SEQ * DM];
__device__ __align__(128) float g_Kr[BATCH * SEQ * DM];
__device__ __align__(128) float g_C [BATCH * SEQ * DM];
__device__ __align__(128) float g_Et[SEQ * DM];

__device__ __forceinline__ int perm8(int k) {
    return (k & ~7) | ((k & 3) << 1) | ((k >> 2) & 1);
}

// cvt.rna.tf32.f32 destination is .b32 (PTX ISA)
__device__ __forceinline__ float rna_tf32(float x) {
    uint32_t r;
    asm("cvt.rna.tf32.f32 %0, %1;" : "=r"(r) : "f"(x));
    return __uint_as_float(r);
}

__device__ __forceinline__ void cpa16(uint32_t dst, const void* src) {
    asm volatile("cp.async.cg.shared.global [%0], [%1], 16;" :: "r"(dst), "l"(src));
}
__device__ __forceinline__ void cpa_commit() {
    asm volatile("cp.async.commit_group;" ::: "memory");
}
template <int N> __device__ __forceinline__ void cpa_wait() {
    asm volatile("cp.async.wait_group %0;" :: "n"(N) : "memory");
}
__device__ __forceinline__ uint32_t smem_u32(const void* p) {
    uint32_t a;
    asm("{ .reg .u64 t; cvta.to.shared.u64 t, %1; cvt.u32.u64 %0, t; }" : "=r"(a) : "l"(p));
    return a;
}

__device__ __forceinline__ void mma_m16n8k8(float* d, const uint32_t* a, const uint32_t* b) {
    asm volatile(
        "mma.sync.aligned.m16n8k8.row.col.f32.tf32.tf32.f32 "
        "{%0,%1,%2,%3}, {%4,%5,%6,%7}, {%8,%9}, {%0,%1,%2,%3};"
        : "+f"(d[0]), "+f"(d[1]), "+f"(d[2]), "+f"(d[3])
        : "r"(a[0]), "r"(a[1]), "r"(a[2]), "r"(a[3]), "r"(b[0]), "r"(b[1]));
}

// ---------------------------------------------------------------------------
// Merged prep kernel (unchanged — works, ~5 µs)
// ---------------------------------------------------------------------------
__global__ __launch_bounds__(128) void prep_kernel(const float* __restrict__ q,
                                                   const float* __restrict__ k,
                                                   const float* __restrict__ E) {
    const int row = blockIdx.x;
    const int i   = row & (SEQ - 1);
    const float* __restrict__ qrow = q    + (size_t)row * DM;
    const float* __restrict__ krow = k    + (size_t)row * DM;
    float* __restrict__ qr         = g_Qr + (size_t)row * DM;
    float* __restrict__ kr         = g_Kr + (size_t)row * DM;
    float* __restrict__ cr         = g_C  + (size_t)row * DM;

    __shared__ float sq[DM];
    __shared__ float red[128];
    const int t = threadIdx.x;

    float partial = 0.0f;
    #pragma unroll
    for (int j = t; j < DM; j += 128) {
        float v = qrow[j];
        sq[j] = v;
        qr[perm8(j)] = rna_tf32(v);
        kr[perm8(j)] = rna_tf32(krow[j]);
        if (j >= i) partial += v;
    }
    red[t] = partial;
    __syncthreads();
    #pragma unroll
    for (int s = 64; s > 0; s >>= 1) {
        if (t < s) red[t] += red[t + s];
        __syncthreads();
    }
    const float suffix = red[0];

    #pragma unroll
    for (int m = t; m < DM; m += 128) {
        float v = (m == 0) ? suffix : ((m <= i) ? sq[i - m] : 0.0f);
        cr[perm8(m)] = rna_tf32(v);
    }

    if (row < SEQ) {   // transpose E: Et[n=row][perm(m)] = rna(E[m][n])
        float* __restrict__ et = g_Et + (size_t)row * DM;
        #pragma unroll
        for (int m = t; m < DM; m += 128)
            et[perm8(m)] = rna_tf32(E[(size_t)m * DM + row]);
    }
}

// ---------------------------------------------------------------------------
// Main GEMM: out[b][m][n] = sum_{kk<1024} A'[m][kk] * B'[n][kk]
// 128x128 CTA tile, BK=32, 3-stage cp.async, 16 warps (4x4), warp tile 32x32.
// Same traffic shape as the best run (R7); doubled warps/SMSP to cover
// stage-boundary bubbles.
// ---------------------------------------------------------------------------
#define BM 128
#define BN 128
#define BKF 32
#define NTHREADS 512
#define ROWSZ 40                        // 32 data floats + 8 pad (conflict-free LDS.64)
#define TILEF (BM * ROWSZ)              // 5120 floats
#define STAGEF (2 * TILEF)
#define NSTAGE 3
#define SMEM_BYTES (NSTAGE * STAGEF * 4)   // 122,880 B

__device__ __forceinline__ void load_stage(int s, int buf, int b, int m0, int n0,
                                           uint32_t smem_base, int tid) {
    const int kg0 = (s & 15) * BKF;
    const float* Asrc;
    const float* Bsrc;
    if (s < 16) {
        Asrc = g_Qr + ((size_t)(b * SEQ + m0)) * DM + kg0;
        Bsrc = g_Kr + ((size_t)(b * SEQ + n0)) * DM + kg0;
    } else {
        Asrc = g_C  + ((size_t)(b * SEQ + m0)) * DM + kg0;
        Bsrc = g_Et + (size_t)n0 * DM + kg0;
    }
    const uint32_t abase = smem_base + buf * (STAGEF * 4);
    const uint32_t bbase = abase + TILEF * 4;

    // each tile: 128 rows x 8 float4 chunks = 1024; 512 threads x 2
    #pragma unroll
    for (int i = 0; i < 2; i++) {
        const int e = tid + i * NTHREADS;
        const int r = e >> 3;
        const int f = e & 7;
        cpa16(abase + (uint32_t)(r * ROWSZ + f * 4) * 4, Asrc + (size_t)r * DM + f * 4);
    }
    #pragma unroll
    for (int i = 0; i < 2; i++) {
        const int e = tid + i * NTHREADS;
        const int r = e >> 3;
        const int f = e & 7;
        cpa16(bbase + (uint32_t)(r * ROWSZ + f * 4) * 4, Bsrc + (size_t)r * DM + f * 4);
    }
}

struct Frag {
    uint32_t a[2][4];
    uint32_t b[4][2];
};

__device__ __forceinline__ void load_frag(Frag& fr, const float* As, const float* Bs,
                                          int k8, int wm, int wn, int grp, int qk) {
    const int kp = k8 * 8 + qk * 2;     // permuted position of (kk, kk+4)
    #pragma unroll
    for (int mi = 0; mi < 2; mi++) {
        const int mrow = wm + mi * 16 + grp;
        const float2 lo = *reinterpret_cast<const float2*>(&As[mrow * ROWSZ + kp]);
        const float2 hi = *reinterpret_cast<const float2*>(&As[(mrow + 8) * ROWSZ + kp]);
        fr.a[mi][0] = __float_as_uint(lo.x);
        fr.a[mi][1] = __float_as_uint(hi.x);
        fr.a[mi][2] = __float_as_uint(lo.y);
        fr.a[mi][3] = __float_as_uint(hi.y);
    }
    #pragma unroll
    for (int ni = 0; ni < 4; ni++) {
        const int ncol = wn + ni * 8 + grp;
        const float2 bb = *reinterpret_cast<const float2*>(&Bs[ncol * ROWSZ + kp]);
        fr.b[ni][0] = __float_as_uint(bb.x);
        fr.b[ni][1] = __float_as_uint(bb.y);
    }
}

__global__ __launch_bounds__(NTHREADS, 1) void gemm_kernel(float* __restrict__ out) {
    extern __shared__ __align__(16) float smem[];
    const uint32_t smem_base = smem_u32(smem);
    const int tid  = threadIdx.x;
    const int wid  = tid >> 5;
    const int lane = tid & 31;
    const int b  = blockIdx.z;
    const int m0 = blockIdx.y * BM;
    const int n0 = blockIdx.x * BN;

    const int wm = (wid >> 2) * 32;     // 0,32,64,96
    const int wn = (wid & 3) * 32;      // 0,32,64,96
    const int grp = lane >> 2;
    const int qk  = lane & 3;

    float acc[2][4][4];
    #pragma unroll
    for (int mi = 0; mi < 2; mi++)
        #pragma unroll
        for (int ni = 0; ni < 4; ni++)
            #pragma unroll
            for (int r = 0; r < 4; r++) acc[mi][ni][r] = 0.0f;

    load_stage(0, 0, b, m0, n0, smem_base, tid); cpa_commit();
    load_stage(1, 1, b, m0, n0, smem_base, tid); cpa_commit();

    Frag fr[2];

    #pragma unroll 1
    for (int s = 0; s < 32; s++) {
        if (s >= 30) cpa_wait<0>(); else cpa_wait<1>();
        __syncthreads();
        if (s + 2 < 32) {
            load_stage(s + 2, (s + 2) % 3, b, m0, n0, smem_base, tid);
            cpa_commit();
        }

        const int buf = s - (s / 3) * 3;
        const float* As = smem + buf * STAGEF;
        const float* Bs = As + TILEF;

        load_frag(fr[0], As, Bs, 0, wm, wn, grp, qk);
        #pragma unroll
        for (int k8 = 0; k8 < 4; k8++) {
            if (k8 < 3)
                load_frag(fr[(k8 + 1) & 1], As, Bs, k8 + 1, wm, wn, grp, qk);
            const Frag& f = fr[k8 & 1];
            #pragma unroll
            for (int mi = 0; mi < 2; mi++)
                #pragma unroll
                for (int ni = 0; ni < 4; ni++)
                    mma_m16n8k8(acc[mi][ni], f.a[mi], f.b[ni]);
        }
    }

    // epilogue
    float* __restrict__ Ob = out + (size_t)b * SEQ * SEQ;
    #pragma unroll
    for (int mi = 0; mi < 2; mi++) {
        const int mr = m0 + wm + mi * 16 + grp;
        #pragma unroll
        for (int ni = 0; ni < 4; ni++) {
            const int nc = n0 + wn + ni * 8 + qk * 2;
            float2 v0 = make_float2(acc[mi][ni][0], acc[mi][ni][1]);
            float2 v1 = make_float2(acc[mi][ni][2], acc[mi][ni][3]);
            *reinterpret_cast<float2*>(&Ob[(size_t)mr * SEQ + nc]) = v0;
            *reinterpret_cast<float2*>(&Ob[(size_t)(mr + 8) * SEQ + nc]) = v1;
        }
    }
}

// ---------------------------------------------------------------------------
extern "C" void kernel_launch(void* const* d_in, const int* in_sizes, int n_in,
                              void* d_out, int out_size) {
    const float* q = (const float*)d_in[0];
    const float* k = (const float*)d_in[1];
    const float* E = (const float*)d_in[2];
    float* out = (float*)d_out;

    cudaFuncSetAttribute(gemm_kernel, cudaFuncAttributeMaxDynamicSharedMemorySize, SMEM_BYTES);

    prep_kernel<<<BATCH * SEQ, 128>>>(q, k, E);

    dim3 grid(SEQ / BN, SEQ / BM, BATCH);
    gemm_kernel<<<grid, NTHREADS, SMEM_BYTES>>>(out);
}

// round 11
// speedup vs baseline: 1.0686x; 1.0489x over previous
#include <cuda_runtime.h>
#include <cstdint>

#define BATCH 8
#define SEQ   512
#define DM    512

// ---------------------------------------------------------------------------
// Scratch, stored with within-8-group k-permutation so mma fragment pairs
// (k, k+4) are adjacent: perm(k) = (k & ~7) | ((k&3)<<1) | ((k>>2)&1)
// ---------------------------------------------------------------------------
__device__ __align__(128) float g_Qr[BATCH * SEQ * DM];
__device__ __align__(128) float g_Kr[BATCH * SEQ * DM];
__device__ __align__(128) float g_C [BATCH * SEQ * DM];
__device__ __align__(128) float g_Et[SEQ * DM];

__device__ __forceinline__ int perm8(int k) {
    return (k & ~7) | ((k & 3) << 1) | ((k >> 2) & 1);
}

__device__ __forceinline__ float rna_tf32(float x) {
    uint32_t r;
    asm("cvt.rna.tf32.f32 %0, %1;" : "=r"(r) : "f"(x));
    return __uint_as_float(r);
}

__device__ __forceinline__ void cpa16(uint32_t dst, const void* src) {
    asm volatile("cp.async.cg.shared.global [%0], [%1], 16;" :: "r"(dst), "l"(src));
}
__device__ __forceinline__ void cpa_commit() {
    asm volatile("cp.async.commit_group;" ::: "memory");
}
template <int N> __device__ __forceinline__ void cpa_wait() {
    asm volatile("cp.async.wait_group %0;" :: "n"(N) : "memory");
}
__device__ __forceinline__ uint32_t smem_u32(const void* p) {
    uint32_t a;
    asm("{ .reg .u64 t; cvta.to.shared.u64 t, %1; cvt.u32.u64 %0, t; }" : "=r"(a) : "l"(p));
    return a;
}
__device__ __forceinline__ void redg_add(float* addr, float v) {
    asm volatile("red.global.add.f32 [%0], %1;" :: "l"(addr), "f"(v) : "memory");
}

__device__ __forceinline__ void mma_m16n8k8(float* d, const uint32_t* a, const uint32_t* b) {
    asm volatile(
        "mma.sync.aligned.m16n8k8.row.col.f32.tf32.tf32.f32 "
        "{%0,%1,%2,%3}, {%4,%5,%6,%7}, {%8,%9}, {%0,%1,%2,%3};"
        : "+f"(d[0]), "+f"(d[1]), "+f"(d[2]), "+f"(d[3])
        : "r"(a[0]), "r"(a[1]), "r"(a[2]), "r"(a[3]), "r"(b[0]), "r"(b[1]));
}

// ---------------------------------------------------------------------------
// Prep kernel, grid = 4096 + 256 blocks of 128 threads.
//  blocks [0, 4096):  Q/K rounding+permute, C build, zero an out slice
//  blocks [4096, 4352): coalesced tiled transpose of E -> g_Et (permuted)
// ---------------------------------------------------------------------------
__global__ __launch_bounds__(128) void prep_kernel(const float* __restrict__ q,
                                                   const float* __restrict__ k,
                                                   const float* __restrict__ E,
                                                   float* __restrict__ out) {
    const int blk = blockIdx.x;
    const int t = threadIdx.x;

    if (blk >= BATCH * SEQ) {
        // ---- E transpose tile (32x32), coalesced both directions ----
        const int tt = blk - BATCH * SEQ;     // 0..255
        const int bx = (tt & 15) * 32;        // n block
        const int by = (tt >> 4) * 32;        // m block
        __shared__ float tile[32][33];
        const int tx = t & 31, ty = t >> 5;   // 4 rows per iteration
        #pragma unroll
        for (int i = 0; i < 8; i++) {
            const int mm = ty + i * 4;
            tile[mm][tx] = E[(size_t)(by + mm) * DM + bx + tx];
        }
        __syncthreads();
        // Et[n][perm(m)] = rna(E[m][n]); perm8(by+tx) = by + perm8(tx)
        #pragma unroll
        for (int i = 0; i < 8; i++) {
            const int nn = ty + i * 4;
            g_Et[(size_t)(bx + nn) * DM + by + perm8(tx)] = rna_tf32(tile[tx][nn]);
        }
        return;
    }

    const int row = blk;
    const int i   = row & (SEQ - 1);
    const float* __restrict__ qrow = q    + (size_t)row * DM;
    const float* __restrict__ krow = k    + (size_t)row * DM;
    float* __restrict__ qr         = g_Qr + (size_t)row * DM;
    float* __restrict__ kr         = g_Kr + (size_t)row * DM;
    float* __restrict__ cr         = g_C  + (size_t)row * DM;

    __shared__ float sq[DM];
    __shared__ float red[128];

    float partial = 0.0f;
    #pragma unroll
    for (int j = t; j < DM; j += 128) {
        float v = qrow[j];
        sq[j] = v;
        qr[perm8(j)] = rna_tf32(v);
        kr[perm8(j)] = rna_tf32(krow[j]);
        if (j >= i) partial += v;
    }
    red[t] = partial;
    __syncthreads();
    #pragma unroll
    for (int s = 64; s > 0; s >>= 1) {
        if (t < s) red[t] += red[t + s];
        __syncthreads();
    }
    const float suffix = red[0];

    #pragma unroll
    for (int m = t; m < DM; m += 128) {
        float v = (m == 0) ? suffix : ((m <= i) ? sq[i - m] : 0.0f);
        cr[perm8(m)] = rna_tf32(v);
    }

    // zero this block's slice of out: total 8*512*512 floats / 4096 blocks
    // = 512 floats = 128 float4 per block
    float4* __restrict__ o4 = reinterpret_cast<float4*>(out) + (size_t)blk * 128;
    const float4 z = make_float4(0.f, 0.f, 0.f, 0.f);
    #pragma unroll
    for (int j = t; j < 128; j += 128) o4[j] = z;
}

// ---------------------------------------------------------------------------
// Main GEMM, K-split by phase:
//  phase 0: out += Q @ K^T  (16 stages),  phase 1: out += C @ E  (skip zero
//  stages: NS1 = min(16, m0/32 + 4)). 128x128 CTA tile, BK=32, 2-stage
//  cp.async (82 KB smem -> 2 CTAs/SM), 8 warps, warp tile 64x32.
//  Output combined with red.global.add.f32 (out pre-zeroed by prep).
// ---------------------------------------------------------------------------
#define BM 128
#define BN 128
#define BKF 32
#define ROWSZ 40                        // 32 data + 8 pad floats
#define TILEF (BM * ROWSZ)              // 5120 floats
#define STAGEF (2 * TILEF)              // 10240 floats
#define NSTAGE 2
#define SMEM_BYTES (NSTAGE * STAGEF * 4)   // 81,920 B

__device__ __forceinline__ void load_stage(int s, int buf, int phase, int b,
                                           int m0, int n0, uint32_t smem_base, int tid) {
    const int kg0 = s * BKF;
    const float* Asrc;
    const float* Bsrc;
    if (phase == 0) {
        Asrc = g_Qr + ((size_t)(b * SEQ + m0)) * DM + kg0;
        Bsrc = g_Kr + ((size_t)(b * SEQ + n0)) * DM + kg0;
    } else {
        Asrc = g_C  + ((size_t)(b * SEQ + m0)) * DM + kg0;
        Bsrc = g_Et + (size_t)n0 * DM + kg0;
    }
    const uint32_t abase = smem_base + buf * (STAGEF * 4);
    const uint32_t bbase = abase + TILEF * 4;

    // each tile: 128 rows x 8 float4 chunks = 1024; 256 threads x 4
    #pragma unroll
    for (int i = 0; i < 4; i++) {
        const int e = tid + i * 256;
        const int r = e >> 3;
        const int f = e & 7;
        cpa16(abase + (uint32_t)(r * ROWSZ + f * 4) * 4, Asrc + (size_t)r * DM + f * 4);
    }
    #pragma unroll
    for (int i = 0; i < 4; i++) {
        const int e = tid + i * 256;
        const int r = e >> 3;
        const int f = e & 7;
        cpa16(bbase + (uint32_t)(r * ROWSZ + f * 4) * 4, Bsrc + (size_t)r * DM + f * 4);
    }
}

struct Frag {
    uint32_t a[4][4];
    uint32_t b[4][2];
};

__device__ __forceinline__ void load_frag(Frag& fr, const float* As, const float* Bs,
                                          int k8, int wm, int wn, int grp, int qk) {
    const int kp = k8 * 8 + qk * 2;     // permuted position of (kk, kk+4)
    #pragma unroll
    for (int mi = 0; mi < 4; mi++) {
        const int mrow = wm + mi * 16 + grp;
        const float2 lo = *reinterpret_cast<const float2*>(&As[mrow * ROWSZ + kp]);
        const float2 hi = *reinterpret_cast<const float2*>(&As[(mrow + 8) * ROWSZ + kp]);
        fr.a[mi][0] = __float_as_uint(lo.x);
        fr.a[mi][1] = __float_as_uint(hi.x);
        fr.a[mi][2] = __float_as_uint(lo.y);
        fr.a[mi][3] = __float_as_uint(hi.y);
    }
    #pragma unroll
    for (int ni = 0; ni < 4; ni++) {
        const int ncol = wn + ni * 8 + grp;
        const float2 bb = *reinterpret_cast<const float2*>(&Bs[ncol * ROWSZ + kp]);
        fr.b[ni][0] = __float_as_uint(bb.x);
        fr.b[ni][1] = __float_as_uint(bb.y);
    }
}

__global__ __launch_bounds__(256, 2) void gemm_kernel(float* __restrict__ out) {
    extern __shared__ __align__(16) float smem[];
    const uint32_t smem_base = smem_u32(smem);
    const int tid  = threadIdx.x;
    const int wid  = tid >> 5;
    const int lane = tid & 31;
    const int b     = blockIdx.z >> 1;
    const int phase = blockIdx.z & 1;
    const int m0 = blockIdx.y * BM;
    const int n0 = blockIdx.x * BN;

    // zero-skip: C[i][m]=0 for m>i, so phase 1 needs kg0 <= m0+127
    const int ns1 = (m0 >> 5) + 4;
    const int NS = (phase == 0) ? 16 : (ns1 < 16 ? ns1 : 16);

    const int wm = (wid >> 2) * 64;     // 0 or 64
    const int wn = (wid & 3) * 32;      // 0,32,64,96
    const int grp = lane >> 2;
    const int qk  = lane & 3;

    float acc[4][4][4];
    #pragma unroll
    for (int mi = 0; mi < 4; mi++)
        #pragma unroll
        for (int ni = 0; ni < 4; ni++)
            #pragma unroll
            for (int r = 0; r < 4; r++) acc[mi][ni][r] = 0.0f;

    load_stage(0, 0, phase, b, m0, n0, smem_base, tid);
    cpa_commit();

    Frag fr[2];

    #pragma unroll 1
    for (int s = 0; s < NS; s++) {
        if (s + 1 < NS) {
            load_stage(s + 1, (s + 1) & 1, phase, b, m0, n0, smem_base, tid);
            cpa_commit();
            cpa_wait<1>();              // stage s complete (only s+1 pending)
        } else {
            cpa_wait<0>();
        }
        __syncthreads();                // all threads' copies of stage s visible

        const float* As = smem + (s & 1) * STAGEF;
        const float* Bs = As + TILEF;

        load_frag(fr[0], As, Bs, 0, wm, wn, grp, qk);
        #pragma unroll
        for (int k8 = 0; k8 < 4; k8++) {
            if (k8 < 3)
                load_frag(fr[(k8 + 1) & 1], As, Bs, k8 + 1, wm, wn, grp, qk);
            const Frag& f = fr[k8 & 1];
            #pragma unroll
            for (int mi = 0; mi < 4; mi++)
                #pragma unroll
                for (int ni = 0; ni < 4; ni++)
                    mma_m16n8k8(acc[mi][ni], f.a[mi], f.b[ni]);
        }
        __syncthreads();                // reads of buf (s&1) done before reuse
    }

    // epilogue: atomically accumulate this phase's contribution
    float* __restrict__ Ob = out + (size_t)b * SEQ * SEQ;
    #pragma unroll
    for (int mi = 0; mi < 4; mi++) {
        const int mr = m0 + wm + mi * 16 + grp;
        #pragma unroll
        for (int ni = 0; ni < 4; ni++) {
            const int nc = n0 + wn + ni * 8 + qk * 2;
            float* p0 = &Ob[(size_t)mr * SEQ + nc];
            float* p1 = &Ob[(size_t)(mr + 8) * SEQ + nc];
            redg_add(p0,     acc[mi][ni][0]);
            redg_add(p0 + 1, acc[mi][ni][1]);
            redg_add(p1,     acc[mi][ni][2]);
            redg_add(p1 + 1, acc[mi][ni][3]);
        }
    }
}

// ---------------------------------------------------------------------------
extern "C" void kernel_launch(void* const* d_in, const int* in_sizes, int n_in,
                              void* d_out, int out_size) {
    const float* q = (const float*)d_in[0];
    const float* k = (const float*)d_in[1];
    const float* E = (const float*)d_in[2];
    float* out = (float*)d_out;

    cudaFuncSetAttribute(gemm_kernel, cudaFuncAttributeMaxDynamicSharedMemorySize, SMEM_BYTES);

    prep_kernel<<<BATCH * SEQ + 256, 128>>>(q, k, E, out);

    dim3 grid(SEQ / BN, SEQ / BM, BATCH * 2);   // z = batch*2 + phase
    gemm_kernel<<<grid, 256, SMEM_BYTES>>>(out);
}